// round 1
// baseline (speedup 1.0000x reference)
#include <cuda_runtime.h>

#define BB 4
#define SS 2048
#define EE 768
#define NHEAD 12
#define HD 64
#define BSROWS (BB*SS)      // 8192
#define QKVN (3*EE)         // 2304

// ---------------- scratch (device globals; no allocation allowed) ----------------
__device__ float g_Wp[EE*QKVN];            // packed [E, 3*N*H]
__device__ float g_q[BB*NHEAD*SS*HD];      // [b,n,s,h]
__device__ float g_k[BB*NHEAD*SS*HD];
__device__ float g_v[BB*NHEAD*SS*HD];
__device__ float g_z[BB*SS*EE];            // [b,s,n*h]

// ---------------- pack W_Q/W_K/W_V -> [E, 2304] ----------------
__global__ void pack_w_kernel(const float* __restrict__ WQ,
                              const float* __restrict__ WK,
                              const float* __restrict__ WV) {
    int idx = blockIdx.x * blockDim.x + threadIdx.x;
    if (idx >= EE * QKVN) return;
    int e   = idx / QKVN;
    int j   = idx - e * QKVN;
    int sel = j / EE;
    int jr  = j - sel * EE;
    int n   = jr >> 6;
    int h   = jr & 63;
    const float* W = (sel == 0) ? WQ : (sel == 1) ? WK : WV;
    g_Wp[idx] = W[(n * EE + e) * HD + h];   // W[n, e, h]
}

// ---------------- QKV SGEMM: x[8192,768] @ Wp[768,2304], scatter to q/k/v ----------------
__global__ __launch_bounds__(256) void qkv_gemm_kernel(
    const float* __restrict__ A,
    const float* __restrict__ bq, const float* __restrict__ bk,
    const float* __restrict__ bv) {
    __shared__ float As[8][128];
    __shared__ float Bs[8][128];

    int tid = threadIdx.x;
    int tx = tid & 15, ty = tid >> 4;
    int rowBlock = blockIdx.y * 128;
    int colBlock = blockIdx.x * 128;

    int aRow = tid >> 1;            // 0..127
    int aCol = (tid & 1) * 4;       // 0 or 4
    int bRow = tid >> 5;            // 0..7
    int bCol = (tid & 31) * 4;      // 0..124

    float acc[8][8];
#pragma unroll
    for (int r = 0; r < 8; r++)
#pragma unroll
        for (int c = 0; c < 8; c++) acc[r][c] = 0.f;

    for (int k0 = 0; k0 < EE; k0 += 8) {
        float4 av = *(const float4*)(A + (size_t)(rowBlock + aRow) * EE + k0 + aCol);
        As[aCol + 0][aRow] = av.x;
        As[aCol + 1][aRow] = av.y;
        As[aCol + 2][aRow] = av.z;
        As[aCol + 3][aRow] = av.w;
        *(float4*)&Bs[bRow][bCol] =
            *(const float4*)(g_Wp + (size_t)(k0 + bRow) * QKVN + colBlock + bCol);
        __syncthreads();
#pragma unroll
        for (int kk = 0; kk < 8; kk++) {
            float a[8], b[8];
            *(float4*)(a)     = *(float4*)&As[kk][ty * 8];
            *(float4*)(a + 4) = *(float4*)&As[kk][ty * 8 + 4];
            *(float4*)(b)     = *(float4*)&Bs[kk][tx * 8];
            *(float4*)(b + 4) = *(float4*)&Bs[kk][tx * 8 + 4];
#pragma unroll
            for (int r = 0; r < 8; r++)
#pragma unroll
                for (int c = 0; c < 8; c++) acc[r][c] += a[r] * b[c];
        }
        __syncthreads();
    }

    // epilogue: scatter to q/k/v [b,n,s,h] (+bias). sel constant per block (768 = 6*128).
    int sel = colBlock / EE;
    const float* bias = (sel == 0) ? bq : (sel == 1) ? bk : bv;
    float* dst = (sel == 0) ? g_q : (sel == 1) ? g_k : g_v;
#pragma unroll
    for (int c = 0; c < 8; c++) {
        int j  = colBlock + tx * 8 + c;
        int jr = j - sel * EE;
        int n  = jr >> 6;
        int h  = jr & 63;
        float bval = bias[jr];
#pragma unroll
        for (int r = 0; r < 8; r++) {
            int row = rowBlock + ty * 8 + r;
            int b_  = row >> 11;        // /2048
            int s_  = row & 2047;
            dst[(((size_t)(b_ * NHEAD + n) * SS) + s_) * HD + h] = acc[r][c] + bval;
        }
    }
}

// ---------------- flash attention: per (b*n, q-tile of 64) ----------------
__global__ __launch_bounds__(256) void flash_kernel() {
    __shared__ float Qs[64][64];   // transposed: Qs[e][i]
    __shared__ float KPs[64][64];  // K transposed [e][j]; reused as P [kk][i]
    __shared__ float Vs[64][64];   // natural [kk][d]

    int tid = threadIdx.x;
    int tx = tid & 15, ty = tid >> 4;
    int bn = blockIdx.y;                 // b*NHEAD + n
    int q0 = blockIdx.x * 64;

    const float* qb = g_q + (size_t)bn * SS * HD;
    const float* kb = g_k + (size_t)bn * SS * HD;
    const float* vb = g_v + (size_t)bn * SS * HD;

    // load Q tile (transposed into smem)
    for (int idx = tid; idx < 64 * 16; idx += 256) {
        int row = idx >> 4;
        int h0  = (idx & 15) << 2;
        float4 qv = *(const float4*)(qb + (size_t)(q0 + row) * HD + h0);
        Qs[h0 + 0][row] = qv.x;
        Qs[h0 + 1][row] = qv.y;
        Qs[h0 + 2][row] = qv.z;
        Qs[h0 + 3][row] = qv.w;
    }

    float m_[4], l_[4], acc[4][4];
#pragma unroll
    for (int r = 0; r < 4; r++) {
        m_[r] = -1e30f;
        l_[r] = 0.f;
#pragma unroll
        for (int c = 0; c < 4; c++) acc[r][c] = 0.f;
    }

    int ntiles = q0 / 64 + 1;    // causal: only tiles with k0 <= q0
    const float scale = 0.125f;  // 1/sqrt(64)

    for (int t = 0; t < ntiles; t++) {
        int k0 = t * 64;
        __syncthreads();   // previous P/V reads complete before overwrite
        // load K tile transposed, V tile natural
        for (int idx = tid; idx < 64 * 16; idx += 256) {
            int row = idx >> 4;
            int h0  = (idx & 15) << 2;
            float4 kv = *(const float4*)(kb + (size_t)(k0 + row) * HD + h0);
            KPs[h0 + 0][row] = kv.x;
            KPs[h0 + 1][row] = kv.y;
            KPs[h0 + 2][row] = kv.z;
            KPs[h0 + 3][row] = kv.w;
            *(float4*)&Vs[row][h0] = *(const float4*)(vb + (size_t)(k0 + row) * HD + h0);
        }
        __syncthreads();

        // S = Q K^T (4x4 per thread)
        float sc[4][4];
#pragma unroll
        for (int r = 0; r < 4; r++)
#pragma unroll
            for (int c = 0; c < 4; c++) sc[r][c] = 0.f;
#pragma unroll 16
        for (int e = 0; e < 64; e++) {
            float4 qv = *(float4*)&Qs[e][ty * 4];
            float4 kv = *(float4*)&KPs[e][tx * 4];
            float qa[4] = {qv.x, qv.y, qv.z, qv.w};
            float ka[4] = {kv.x, kv.y, kv.z, kv.w};
#pragma unroll
            for (int r = 0; r < 4; r++)
#pragma unroll
                for (int c = 0; c < 4; c++) sc[r][c] += qa[r] * ka[c];
        }
#pragma unroll
        for (int r = 0; r < 4; r++)
#pragma unroll
            for (int c = 0; c < 4; c++) sc[r][c] *= scale;

        // causal mask only on the diagonal tile
        if (t == ntiles - 1) {
#pragma unroll
            for (int r = 0; r < 4; r++)
#pragma unroll
                for (int c = 0; c < 4; c++)
                    if (k0 + tx * 4 + c > q0 + ty * 4 + r) sc[r][c] = -1e30f;
        }

        // online softmax (per row; reduce across the 16 tx lanes via xor-shuffle)
        float p[4][4];
#pragma unroll
        for (int r = 0; r < 4; r++) {
            float mx = fmaxf(fmaxf(sc[r][0], sc[r][1]), fmaxf(sc[r][2], sc[r][3]));
#pragma unroll
            for (int o = 8; o >= 1; o >>= 1)
                mx = fmaxf(mx, __shfl_xor_sync(0xffffffffu, mx, o));
            float mnew  = fmaxf(m_[r], mx);
            float alpha = __expf(m_[r] - mnew);
            float rs = 0.f;
#pragma unroll
            for (int c = 0; c < 4; c++) {
                p[r][c] = __expf(sc[r][c] - mnew);
                rs += p[r][c];
            }
#pragma unroll
            for (int o = 8; o >= 1; o >>= 1)
                rs += __shfl_xor_sync(0xffffffffu, rs, o);
            l_[r] = l_[r] * alpha + rs;
            m_[r] = mnew;
#pragma unroll
            for (int c = 0; c < 4; c++) acc[r][c] *= alpha;
        }

        __syncthreads();   // done reading KPs as K
        // write P transposed into KPs: P[kk][i]
#pragma unroll
        for (int r = 0; r < 4; r++)
#pragma unroll
            for (int c = 0; c < 4; c++)
                KPs[tx * 4 + c][ty * 4 + r] = p[r][c];
        __syncthreads();

        // O += P @ V
#pragma unroll 16
        for (int kk = 0; kk < 64; kk++) {
            float4 pv = *(float4*)&KPs[kk][ty * 4];
            float4 vv = *(float4*)&Vs[kk][tx * 4];
            float pa[4] = {pv.x, pv.y, pv.z, pv.w};
            float va[4] = {vv.x, vv.y, vv.z, vv.w};
#pragma unroll
            for (int r = 0; r < 4; r++)
#pragma unroll
                for (int c = 0; c < 4; c++) acc[r][c] += pa[r] * va[c];
        }
    }

    // epilogue: z[b, s, n, h]
    int b_ = bn / NHEAD;
    int n_ = bn - b_ * NHEAD;
#pragma unroll
    for (int r = 0; r < 4; r++) {
        int s_ = q0 + ty * 4 + r;
        float inv = 1.f / l_[r];
#pragma unroll
        for (int c = 0; c < 4; c++) {
            int h = tx * 4 + c;
            g_z[(((size_t)(b_ * SS + s_)) * NHEAD + n_) * HD + h] = acc[r][c] * inv;
        }
    }
}

// ---------------- output SGEMM: z[8192,768] @ W_O[768,768] + b_O -> out ----------------
__global__ __launch_bounds__(256) void out_gemm_kernel(
    const float* __restrict__ Bm, const float* __restrict__ bo,
    float* __restrict__ C) {
    __shared__ float As[8][128];
    __shared__ float Bs[8][128];

    int tid = threadIdx.x;
    int tx = tid & 15, ty = tid >> 4;
    int rowBlock = blockIdx.y * 128;
    int colBlock = blockIdx.x * 128;

    int aRow = tid >> 1;
    int aCol = (tid & 1) * 4;
    int bRow = tid >> 5;
    int bCol = (tid & 31) * 4;

    float acc[8][8];
#pragma unroll
    for (int r = 0; r < 8; r++)
#pragma unroll
        for (int c = 0; c < 8; c++) acc[r][c] = 0.f;

    for (int k0 = 0; k0 < EE; k0 += 8) {
        float4 av = *(const float4*)(g_z + (size_t)(rowBlock + aRow) * EE + k0 + aCol);
        As[aCol + 0][aRow] = av.x;
        As[aCol + 1][aRow] = av.y;
        As[aCol + 2][aRow] = av.z;
        As[aCol + 3][aRow] = av.w;
        *(float4*)&Bs[bRow][bCol] =
            *(const float4*)(Bm + (size_t)(k0 + bRow) * EE + colBlock + bCol);
        __syncthreads();
#pragma unroll
        for (int kk = 0; kk < 8; kk++) {
            float a[8], b[8];
            *(float4*)(a)     = *(float4*)&As[kk][ty * 8];
            *(float4*)(a + 4) = *(float4*)&As[kk][ty * 8 + 4];
            *(float4*)(b)     = *(float4*)&Bs[kk][tx * 8];
            *(float4*)(b + 4) = *(float4*)&Bs[kk][tx * 8 + 4];
#pragma unroll
            for (int r = 0; r < 8; r++)
#pragma unroll
                for (int c = 0; c < 8; c++) acc[r][c] += a[r] * b[c];
        }
        __syncthreads();
    }

#pragma unroll
    for (int c = 0; c < 8; c++) {
        int col = colBlock + tx * 8 + c;
        float bval = bo[col];
#pragma unroll
        for (int r = 0; r < 8; r++) {
            int row = rowBlock + ty * 8 + r;
            C[(size_t)row * EE + col] = acc[r][c] + bval;
        }
    }
}

// ---------------- launch ----------------
extern "C" void kernel_launch(void* const* d_in, const int* in_sizes, int n_in,
                              void* d_out, int out_size) {
    const float* x  = (const float*)d_in[0];
    const float* WQ = (const float*)d_in[1];
    const float* WK = (const float*)d_in[2];
    const float* WV = (const float*)d_in[3];
    const float* WO = (const float*)d_in[4];
    const float* bq = (const float*)d_in[5];
    const float* bk = (const float*)d_in[6];
    const float* bv = (const float*)d_in[7];
    const float* bo = (const float*)d_in[8];
    float* out = (float*)d_out;

    pack_w_kernel<<<(EE * QKVN + 255) / 256, 256>>>(WQ, WK, WV);
    qkv_gemm_kernel<<<dim3(QKVN / 128, BSROWS / 128), 256>>>(x, bq, bk, bv);
    flash_kernel<<<dim3(SS / 64, BB * NHEAD), 256>>>();
    out_gemm_kernel<<<dim3(EE / 128, BSROWS / 128), 256>>>(WO, bo, out);
}

// round 2
// speedup vs baseline: 3.2170x; 3.2170x over previous
#include <cuda_runtime.h>
#include <cstdint>

#define BB 4
#define SS 2048
#define EE 768
#define NHEAD 12
#define HD 64
#define BSROWS (BB*SS)      // 8192
#define QKVN (3*EE)         // 2304

// ---------------- scratch ----------------
__device__ float g_Wp[EE*QKVN];            // packed [E, 3*N*H]
__device__ float g_q[BB*NHEAD*SS*HD];      // [b,n,s,h]
__device__ float g_k[BB*NHEAD*SS*HD];
__device__ float g_v[BB*NHEAD*SS*HD];
__device__ float g_z[BB*SS*EE];            // [b,s,n*h]

// ---------------- helpers ----------------
__device__ __forceinline__ uint32_t f2tf(float x) {
    uint32_t u;
    asm("cvt.rna.tf32.f32 %0, %1;" : "=r"(u) : "f"(x));
    return u;
}
__device__ __forceinline__ float f2tff(float x) {
    return __uint_as_float(f2tf(x));
}
__device__ __forceinline__ void mma8(float* c, const uint32_t* a, uint32_t b0, uint32_t b1) {
    asm volatile(
        "mma.sync.aligned.m16n8k8.row.col.f32.tf32.tf32.f32 "
        "{%0,%1,%2,%3},{%4,%5,%6,%7},{%8,%9},{%0,%1,%2,%3};"
        : "+f"(c[0]), "+f"(c[1]), "+f"(c[2]), "+f"(c[3])
        : "r"(a[0]), "r"(a[1]), "r"(a[2]), "r"(a[3]), "r"(b0), "r"(b1));
}

// ---------------- pack W_Q/W_K/W_V -> [E, 2304] ----------------
__global__ void pack_w_kernel(const float* __restrict__ WQ,
                              const float* __restrict__ WK,
                              const float* __restrict__ WV) {
    int idx = blockIdx.x * blockDim.x + threadIdx.x;
    if (idx >= EE * QKVN) return;
    int e   = idx / QKVN;
    int j   = idx - e * QKVN;
    int sel = j / EE;
    int jr  = j - sel * EE;
    int n   = jr >> 6;
    int h   = jr & 63;
    const float* W = (sel == 0) ? WQ : (sel == 1) ? WK : WV;
    g_Wp[idx] = W[(n * EE + e) * HD + h];
}

// ---------------- TF32 tensor-core GEMM: x[8192,768] @ Wp[768,2304] -> q/k/v ----------------
// BM=128 BN=128 BK=16, 8 warps as 2(m) x 4(n), warp tile 64x32 (mt=4, nt=4)
__global__ __launch_bounds__(256, 2) void qkv_gemm_kernel(
    const float* __restrict__ A,
    const float* __restrict__ bq, const float* __restrict__ bk,
    const float* __restrict__ bv) {
    __shared__ float As[128][20];   // [m][k] pitch 20
    __shared__ float Bs[16][132];   // [k][n] pitch 132

    int tid = threadIdx.x;
    int wid = tid >> 5, lane = tid & 31;
    int g = lane >> 2, t = lane & 3;
    int warpM = wid >> 2, warpN = wid & 3;
    int rowBlock = blockIdx.y * 128;
    int colBlock = blockIdx.x * 128;

    int aRow = tid >> 1, aK = (tid & 1) * 8;
    int bRow = tid >> 4, bCol = (tid & 15) * 8;

    const float* aPtr = A + (size_t)(rowBlock + aRow) * EE + aK;
    const float* bPtr = g_Wp + (size_t)bRow * QKVN + colBlock + bCol;

    float4 ra0 = *(const float4*)(aPtr);
    float4 ra1 = *(const float4*)(aPtr + 4);
    float4 rb0 = *(const float4*)(bPtr);
    float4 rb1 = *(const float4*)(bPtr + 4);

    float acc[4][4][4];
#pragma unroll
    for (int mt = 0; mt < 4; mt++)
#pragma unroll
        for (int nt = 0; nt < 4; nt++)
#pragma unroll
            for (int i = 0; i < 4; i++) acc[mt][nt][i] = 0.f;

    for (int k0 = 0; k0 < EE; k0 += 16) {
        As[aRow][aK + 0] = f2tff(ra0.x); As[aRow][aK + 1] = f2tff(ra0.y);
        As[aRow][aK + 2] = f2tff(ra0.z); As[aRow][aK + 3] = f2tff(ra0.w);
        As[aRow][aK + 4] = f2tff(ra1.x); As[aRow][aK + 5] = f2tff(ra1.y);
        As[aRow][aK + 6] = f2tff(ra1.z); As[aRow][aK + 7] = f2tff(ra1.w);
        Bs[bRow][bCol + 0] = f2tff(rb0.x); Bs[bRow][bCol + 1] = f2tff(rb0.y);
        Bs[bRow][bCol + 2] = f2tff(rb0.z); Bs[bRow][bCol + 3] = f2tff(rb0.w);
        Bs[bRow][bCol + 4] = f2tff(rb1.x); Bs[bRow][bCol + 5] = f2tff(rb1.y);
        Bs[bRow][bCol + 6] = f2tff(rb1.z); Bs[bRow][bCol + 7] = f2tff(rb1.w);
        __syncthreads();

        if (k0 + 16 < EE) {
            ra0 = *(const float4*)(aPtr + k0 + 16);
            ra1 = *(const float4*)(aPtr + k0 + 20);
            rb0 = *(const float4*)(bPtr + (size_t)(k0 + 16) * QKVN);
            rb1 = *(const float4*)(bPtr + (size_t)(k0 + 16) * QKVN + 4);
        }

#pragma unroll
        for (int ks = 0; ks < 2; ks++) {
            uint32_t af[4][4];
#pragma unroll
            for (int mt = 0; mt < 4; mt++) {
                int mb = warpM * 64 + mt * 16;
                af[mt][0] = __float_as_uint(As[mb + g][ks * 8 + t]);
                af[mt][1] = __float_as_uint(As[mb + g + 8][ks * 8 + t]);
                af[mt][2] = __float_as_uint(As[mb + g][ks * 8 + t + 4]);
                af[mt][3] = __float_as_uint(As[mb + g + 8][ks * 8 + t + 4]);
            }
            uint32_t bf[4][2];
#pragma unroll
            for (int nt = 0; nt < 4; nt++) {
                int nb = warpN * 32 + nt * 8 + g;
                bf[nt][0] = __float_as_uint(Bs[ks * 8 + t][nb]);
                bf[nt][1] = __float_as_uint(Bs[ks * 8 + t + 4][nb]);
            }
#pragma unroll
            for (int mt = 0; mt < 4; mt++)
#pragma unroll
                for (int nt = 0; nt < 4; nt++)
                    mma8(acc[mt][nt], af[mt], bf[nt][0], bf[nt][1]);
        }
        __syncthreads();
    }

    // epilogue: scatter into q/k/v [b,n,s,h] + bias
    int sel = colBlock / EE;
    const float* bias = (sel == 0) ? bq : (sel == 1) ? bk : bv;
    float* dst = (sel == 0) ? g_q : (sel == 1) ? g_k : g_v;
#pragma unroll
    for (int mt = 0; mt < 4; mt++) {
#pragma unroll
        for (int nt = 0; nt < 4; nt++) {
            int j  = colBlock + warpN * 32 + nt * 8 + 2 * t;
            int jr = j - sel * EE;
            int n  = jr >> 6;
            int h  = jr & 63;
            float b0 = bias[jr], b1 = bias[jr + 1];
            int r0 = rowBlock + warpM * 64 + mt * 16 + g;
            int r1 = r0 + 8;
            int bb0 = r0 >> 11, s0 = r0 & 2047;
            int bb1 = r1 >> 11, s1 = r1 & 2047;
            float2 v0 = make_float2(acc[mt][nt][0] + b0, acc[mt][nt][1] + b1);
            float2 v1 = make_float2(acc[mt][nt][2] + b0, acc[mt][nt][3] + b1);
            *(float2*)(dst + (((size_t)(bb0 * NHEAD + n) * SS) + s0) * HD + h) = v0;
            *(float2*)(dst + (((size_t)(bb1 * NHEAD + n) * SS) + s1) * HD + h) = v1;
        }
    }
}

// ---------------- flash attention (TF32 mma): q-tile 128, k-tile 64, 8 warps (16 q-rows each) ----------------
__global__ __launch_bounds__(256, 1) void flash_kernel() {
    __shared__ float Ks[64][68];  // [s][h] tf32
    __shared__ float Vs[64][68];  // [s][h] tf32

    int tid = threadIdx.x;
    int wid = tid >> 5, lane = tid & 31;
    int g = lane >> 2, t = lane & 3;
    int bn = blockIdx.y;
    int qt = gridDim.x - 1 - blockIdx.x;   // heavy blocks first
    int q0 = qt * 128;

    const float* qb = g_q + (size_t)bn * SS * HD;
    const float* kb = g_k + (size_t)bn * SS * HD;
    const float* vb = g_v + (size_t)bn * SS * HD;

    // Q fragments in registers for the whole loop (pre-scaled by 1/sqrt(64))
    int qrow = q0 + wid * 16;
    uint32_t qf[8][4];
#pragma unroll
    for (int ks = 0; ks < 8; ks++) {
        qf[ks][0] = f2tf(0.125f * qb[(size_t)(qrow + g) * HD + ks * 8 + t]);
        qf[ks][1] = f2tf(0.125f * qb[(size_t)(qrow + g + 8) * HD + ks * 8 + t]);
        qf[ks][2] = f2tf(0.125f * qb[(size_t)(qrow + g) * HD + ks * 8 + t + 4]);
        qf[ks][3] = f2tf(0.125f * qb[(size_t)(qrow + g + 8) * HD + ks * 8 + t + 4]);
    }

    float acc[8][4];
#pragma unroll
    for (int nt = 0; nt < 8; nt++)
#pragma unroll
        for (int i = 0; i < 4; i++) acc[nt][i] = 0.f;
    float m0 = -1e30f, m1 = -1e30f, l0 = 0.f, l1 = 0.f;

    int ntk = 2 * qt + 2;
    int r0 = qrow + g, r1 = qrow + g + 8;

    for (int kt = 0; kt < ntk; kt++) {
        int k0 = kt * 64;
        __syncthreads();
#pragma unroll
        for (int i = 0; i < 4; i++) {
            int idx = i * 256 + tid;
            int row = idx >> 4;
            int col = (idx & 15) * 4;
            float4 kv = *(const float4*)(kb + (size_t)(k0 + row) * HD + col);
            float4 vv = *(const float4*)(vb + (size_t)(k0 + row) * HD + col);
            Ks[row][col + 0] = f2tff(kv.x); Ks[row][col + 1] = f2tff(kv.y);
            Ks[row][col + 2] = f2tff(kv.z); Ks[row][col + 3] = f2tff(kv.w);
            Vs[row][col + 0] = f2tff(vv.x); Vs[row][col + 1] = f2tff(vv.y);
            Vs[row][col + 2] = f2tff(vv.z); Vs[row][col + 3] = f2tff(vv.w);
        }
        __syncthreads();

        // S = Q K^T
        float sc[8][4];
#pragma unroll
        for (int nt = 0; nt < 8; nt++)
#pragma unroll
            for (int i = 0; i < 4; i++) sc[nt][i] = 0.f;
#pragma unroll
        for (int nt = 0; nt < 8; nt++) {
#pragma unroll
            for (int ks = 0; ks < 8; ks++) {
                uint32_t b0 = __float_as_uint(Ks[nt * 8 + g][ks * 8 + t]);
                uint32_t b1 = __float_as_uint(Ks[nt * 8 + g][ks * 8 + t + 4]);
                mma8(sc[nt], qf[ks], b0, b1);
            }
        }

        // causal mask (only the two diagonal-region tiles need it)
        if (kt >= 2 * qt) {
#pragma unroll
            for (int nt = 0; nt < 8; nt++) {
                int cA = k0 + nt * 8 + 2 * t;
                int cB = cA + 1;
                if (cA > r0) sc[nt][0] = -1e30f;
                if (cB > r0) sc[nt][1] = -1e30f;
                if (cA > r1) sc[nt][2] = -1e30f;
                if (cB > r1) sc[nt][3] = -1e30f;
            }
        }

        // online softmax (rows are quad-local: lanes xor 1,2)
        float rm0 = -1e30f, rm1 = -1e30f;
#pragma unroll
        for (int nt = 0; nt < 8; nt++) {
            rm0 = fmaxf(rm0, fmaxf(sc[nt][0], sc[nt][1]));
            rm1 = fmaxf(rm1, fmaxf(sc[nt][2], sc[nt][3]));
        }
        rm0 = fmaxf(rm0, __shfl_xor_sync(0xffffffffu, rm0, 1));
        rm0 = fmaxf(rm0, __shfl_xor_sync(0xffffffffu, rm0, 2));
        rm1 = fmaxf(rm1, __shfl_xor_sync(0xffffffffu, rm1, 1));
        rm1 = fmaxf(rm1, __shfl_xor_sync(0xffffffffu, rm1, 2));
        float mn0 = fmaxf(m0, rm0), mn1 = fmaxf(m1, rm1);
        float al0 = __expf(m0 - mn0), al1 = __expf(m1 - mn1);
        m0 = mn0; m1 = mn1;

        float rs0 = 0.f, rs1 = 0.f;
#pragma unroll
        for (int nt = 0; nt < 8; nt++) {
            sc[nt][0] = __expf(sc[nt][0] - m0); rs0 += sc[nt][0];
            sc[nt][1] = __expf(sc[nt][1] - m0); rs0 += sc[nt][1];
            sc[nt][2] = __expf(sc[nt][2] - m1); rs1 += sc[nt][2];
            sc[nt][3] = __expf(sc[nt][3] - m1); rs1 += sc[nt][3];
        }
        rs0 += __shfl_xor_sync(0xffffffffu, rs0, 1);
        rs0 += __shfl_xor_sync(0xffffffffu, rs0, 2);
        rs1 += __shfl_xor_sync(0xffffffffu, rs1, 1);
        rs1 += __shfl_xor_sync(0xffffffffu, rs1, 2);
        l0 = l0 * al0 + rs0;
        l1 = l1 * al1 + rs1;
#pragma unroll
        for (int nt = 0; nt < 8; nt++) {
            acc[nt][0] *= al0; acc[nt][1] *= al0;
            acc[nt][2] *= al1; acc[nt][3] *= al1;
        }

        // O += P @ V  (P transposed C-frag -> A-frag via quad shuffles)
        int src  = g * 4 + (t >> 1);
        int src2 = src + 2;
#pragma unroll
        for (int j = 0; j < 8; j++) {
            float x0 = __shfl_sync(0xffffffffu, sc[j][0], src);
            float x1 = __shfl_sync(0xffffffffu, sc[j][1], src);
            float y0 = __shfl_sync(0xffffffffu, sc[j][0], src2);
            float y1 = __shfl_sync(0xffffffffu, sc[j][1], src2);
            float z0 = __shfl_sync(0xffffffffu, sc[j][2], src);
            float z1 = __shfl_sync(0xffffffffu, sc[j][3], src);
            float w0 = __shfl_sync(0xffffffffu, sc[j][2], src2);
            float w1 = __shfl_sync(0xffffffffu, sc[j][3], src2);
            uint32_t pa[4];
            pa[0] = f2tf((t & 1) ? x1 : x0);
            pa[1] = f2tf((t & 1) ? z1 : z0);
            pa[2] = f2tf((t & 1) ? y1 : y0);
            pa[3] = f2tf((t & 1) ? w1 : w0);
#pragma unroll
            for (int hd = 0; hd < 8; hd++) {
                uint32_t b0 = __float_as_uint(Vs[j * 8 + t][hd * 8 + g]);
                uint32_t b1 = __float_as_uint(Vs[j * 8 + t + 4][hd * 8 + g]);
                mma8(acc[hd], pa, b0, b1);
            }
        }
    }

    // epilogue -> g_z[b, s, n*64+h]
    int b_ = bn / NHEAD;
    int n_ = bn - b_ * NHEAD;
    float inv0 = 1.f / l0, inv1 = 1.f / l1;
#pragma unroll
    for (int hd = 0; hd < 8; hd++) {
        int h = hd * 8 + 2 * t;
        float2 o0 = make_float2(acc[hd][0] * inv0, acc[hd][1] * inv0);
        float2 o1 = make_float2(acc[hd][2] * inv1, acc[hd][3] * inv1);
        *(float2*)(g_z + ((size_t)(b_ * SS + r0) * NHEAD + n_) * HD + h) = o0;
        *(float2*)(g_z + ((size_t)(b_ * SS + r1) * NHEAD + n_) * HD + h) = o1;
    }
}

// ---------------- output GEMM: z[8192,768] @ W_O[768,768] + b_O ----------------
__global__ __launch_bounds__(256, 2) void out_gemm_kernel(
    const float* __restrict__ Bm, const float* __restrict__ bo,
    float* __restrict__ C) {
    __shared__ float As[128][20];
    __shared__ float Bs[16][132];

    int tid = threadIdx.x;
    int wid = tid >> 5, lane = tid & 31;
    int g = lane >> 2, t = lane & 3;
    int warpM = wid >> 2, warpN = wid & 3;
    int rowBlock = blockIdx.y * 128;
    int colBlock = blockIdx.x * 128;

    int aRow = tid >> 1, aK = (tid & 1) * 8;
    int bRow = tid >> 4, bCol = (tid & 15) * 8;

    const float* aPtr = g_z + (size_t)(rowBlock + aRow) * EE + aK;
    const float* bPtr = Bm + (size_t)bRow * EE + colBlock + bCol;

    float4 ra0 = *(const float4*)(aPtr);
    float4 ra1 = *(const float4*)(aPtr + 4);
    float4 rb0 = *(const float4*)(bPtr);
    float4 rb1 = *(const float4*)(bPtr + 4);

    float acc[4][4][4];
#pragma unroll
    for (int mt = 0; mt < 4; mt++)
#pragma unroll
        for (int nt = 0; nt < 4; nt++)
#pragma unroll
            for (int i = 0; i < 4; i++) acc[mt][nt][i] = 0.f;

    for (int k0 = 0; k0 < EE; k0 += 16) {
        As[aRow][aK + 0] = f2tff(ra0.x); As[aRow][aK + 1] = f2tff(ra0.y);
        As[aRow][aK + 2] = f2tff(ra0.z); As[aRow][aK + 3] = f2tff(ra0.w);
        As[aRow][aK + 4] = f2tff(ra1.x); As[aRow][aK + 5] = f2tff(ra1.y);
        As[aRow][aK + 6] = f2tff(ra1.z); As[aRow][aK + 7] = f2tff(ra1.w);
        Bs[bRow][bCol + 0] = f2tff(rb0.x); Bs[bRow][bCol + 1] = f2tff(rb0.y);
        Bs[bRow][bCol + 2] = f2tff(rb0.z); Bs[bRow][bCol + 3] = f2tff(rb0.w);
        Bs[bRow][bCol + 4] = f2tff(rb1.x); Bs[bRow][bCol + 5] = f2tff(rb1.y);
        Bs[bRow][bCol + 6] = f2tff(rb1.z); Bs[bRow][bCol + 7] = f2tff(rb1.w);
        __syncthreads();

        if (k0 + 16 < EE) {
            ra0 = *(const float4*)(aPtr + k0 + 16);
            ra1 = *(const float4*)(aPtr + k0 + 20);
            rb0 = *(const float4*)(bPtr + (size_t)(k0 + 16) * EE);
            rb1 = *(const float4*)(bPtr + (size_t)(k0 + 16) * EE + 4);
        }

#pragma unroll
        for (int ks = 0; ks < 2; ks++) {
            uint32_t af[4][4];
#pragma unroll
            for (int mt = 0; mt < 4; mt++) {
                int mb = warpM * 64 + mt * 16;
                af[mt][0] = __float_as_uint(As[mb + g][ks * 8 + t]);
                af[mt][1] = __float_as_uint(As[mb + g + 8][ks * 8 + t]);
                af[mt][2] = __float_as_uint(As[mb + g][ks * 8 + t + 4]);
                af[mt][3] = __float_as_uint(As[mb + g + 8][ks * 8 + t + 4]);
            }
            uint32_t bf[4][2];
#pragma unroll
            for (int nt = 0; nt < 4; nt++) {
                int nb = warpN * 32 + nt * 8 + g;
                bf[nt][0] = __float_as_uint(Bs[ks * 8 + t][nb]);
                bf[nt][1] = __float_as_uint(Bs[ks * 8 + t + 4][nb]);
            }
#pragma unroll
            for (int mt = 0; mt < 4; mt++)
#pragma unroll
                for (int nt = 0; nt < 4; nt++)
                    mma8(acc[mt][nt], af[mt], bf[nt][0], bf[nt][1]);
        }
        __syncthreads();
    }

#pragma unroll
    for (int mt = 0; mt < 4; mt++) {
#pragma unroll
        for (int nt = 0; nt < 4; nt++) {
            int col = colBlock + warpN * 32 + nt * 8 + 2 * t;
            float b0 = bo[col], b1 = bo[col + 1];
            int r0 = rowBlock + warpM * 64 + mt * 16 + g;
            int r1 = r0 + 8;
            *(float2*)(C + (size_t)r0 * EE + col) =
                make_float2(acc[mt][nt][0] + b0, acc[mt][nt][1] + b1);
            *(float2*)(C + (size_t)r1 * EE + col) =
                make_float2(acc[mt][nt][2] + b0, acc[mt][nt][3] + b1);
        }
    }
}

// ---------------- launch ----------------
extern "C" void kernel_launch(void* const* d_in, const int* in_sizes, int n_in,
                              void* d_out, int out_size) {
    const float* x  = (const float*)d_in[0];
    const float* WQ = (const float*)d_in[1];
    const float* WK = (const float*)d_in[2];
    const float* WV = (const float*)d_in[3];
    const float* WO = (const float*)d_in[4];
    const float* bq = (const float*)d_in[5];
    const float* bk = (const float*)d_in[6];
    const float* bv = (const float*)d_in[7];
    const float* bo = (const float*)d_in[8];
    float* out = (float*)d_out;

    pack_w_kernel<<<(EE * QKVN + 255) / 256, 256>>>(WQ, WK, WV);
    qkv_gemm_kernel<<<dim3(QKVN / 128, BSROWS / 128), 256>>>(x, bq, bk, bv);
    flash_kernel<<<dim3(SS / 128, BB * NHEAD), 256>>>();
    out_gemm_kernel<<<dim3(EE / 128, BSROWS / 128), 256>>>(WO, bo, out);
}

// round 3
// speedup vs baseline: 3.6811x; 1.1443x over previous
#include <cuda_runtime.h>
#include <cstdint>

#define BB 4
#define SS 2048
#define EE 768
#define NHEAD 12
#define HD 64
#define BSROWS (BB*SS)      // 8192
#define QKVN (3*EE)         // 2304

// ---------------- scratch ----------------
__device__ float g_Wp[EE*QKVN];            // packed [E, 3*N*H]
__device__ float g_q[BB*NHEAD*SS*HD];      // [b,n,s,h]
__device__ float g_k[BB*NHEAD*SS*HD];
__device__ float g_v[BB*NHEAD*SS*HD];
__device__ float g_z[BB*SS*EE];            // [b,s,n*h]

// ---------------- helpers ----------------
__device__ __forceinline__ uint32_t f2tf(float x) {
    uint32_t u;
    asm("cvt.rna.tf32.f32 %0, %1;" : "=r"(u) : "f"(x));
    return u;
}
__device__ __forceinline__ float f2tff(float x) {
    return __uint_as_float(f2tf(x));
}
__device__ __forceinline__ float4 f2tf4(float4 v) {
    return make_float4(f2tff(v.x), f2tff(v.y), f2tff(v.z), f2tff(v.w));
}
__device__ __forceinline__ void mma8(float* c, const uint32_t* a, uint32_t b0, uint32_t b1) {
    asm volatile(
        "mma.sync.aligned.m16n8k8.row.col.f32.tf32.tf32.f32 "
        "{%0,%1,%2,%3},{%4,%5,%6,%7},{%8,%9},{%0,%1,%2,%3};"
        : "+f"(c[0]), "+f"(c[1]), "+f"(c[2]), "+f"(c[3])
        : "r"(a[0]), "r"(a[1]), "r"(a[2]), "r"(a[3]), "r"(b0), "r"(b1));
}

// ---------------- pack W_Q/W_K/W_V -> [E, 2304] ----------------
__global__ void pack_w_kernel(const float* __restrict__ WQ,
                              const float* __restrict__ WK,
                              const float* __restrict__ WV) {
    int idx = blockIdx.x * blockDim.x + threadIdx.x;
    if (idx >= EE * QKVN) return;
    int e   = idx / QKVN;
    int j   = idx - e * QKVN;
    int sel = j / EE;
    int jr  = j - sel * EE;
    int n   = jr >> 6;
    int h   = jr & 63;
    const float* W = (sel == 0) ? WQ : (sel == 1) ? WK : WV;
    g_Wp[idx] = W[(n * EE + e) * HD + h];
}

// ======== shared GEMM core (BM=128 BN=128 BK=16, 8 warps 2x4, warp 64x32) ========
#define GEMM_COMPUTE(ASBUF, BSBUF)                                                  \
    _Pragma("unroll")                                                               \
    for (int ks = 0; ks < 2; ks++) {                                                \
        uint32_t af[4][4];                                                          \
        _Pragma("unroll")                                                           \
        for (int mt = 0; mt < 4; mt++) {                                            \
            int mb = warpM * 64 + mt * 16;                                          \
            af[mt][0] = __float_as_uint(ASBUF[mb + g][ks * 8 + t]);                 \
            af[mt][1] = __float_as_uint(ASBUF[mb + g + 8][ks * 8 + t]);             \
            af[mt][2] = __float_as_uint(ASBUF[mb + g][ks * 8 + t + 4]);             \
            af[mt][3] = __float_as_uint(ASBUF[mb + g + 8][ks * 8 + t + 4]);         \
        }                                                                           \
        uint32_t bf[4][2];                                                          \
        _Pragma("unroll")                                                           \
        for (int nt = 0; nt < 4; nt++) {                                            \
            int nb = warpN * 32 + nt * 8 + g;                                       \
            bf[nt][0] = __float_as_uint(BSBUF[ks * 8 + t][nb]);                     \
            bf[nt][1] = __float_as_uint(BSBUF[ks * 8 + t + 4][nb]);                 \
        }                                                                           \
        _Pragma("unroll")                                                           \
        for (int mt = 0; mt < 4; mt++)                                              \
            _Pragma("unroll")                                                       \
            for (int nt = 0; nt < 4; nt++)                                          \
                mma8(acc[mt][nt], af[mt], bf[nt][0], bf[nt][1]);                    \
    }

// ---------------- QKV GEMM ----------------
__global__ __launch_bounds__(256, 2) void qkv_gemm_kernel(
    const float* __restrict__ A,
    const float* __restrict__ bq, const float* __restrict__ bk,
    const float* __restrict__ bv) {
    __shared__ float As[2][128][20];
    __shared__ float Bs[2][16][136];

    int tid = threadIdx.x;
    int wid = tid >> 5, lane = tid & 31;
    int g = lane >> 2, t = lane & 3;
    int warpM = wid >> 2, warpN = wid & 3;
    int rowBlock = blockIdx.y * 128;
    int colBlock = blockIdx.x * 128;

    int aRow = tid >> 1, aK = (tid & 1) * 8;
    int bRow = tid >> 4, bCol = (tid & 15) * 8;

    const float* aPtr = A + (size_t)(rowBlock + aRow) * EE + aK;
    const float* bPtr = g_Wp + (size_t)bRow * QKVN + colBlock + bCol;

    float acc[4][4][4];
#pragma unroll
    for (int mt = 0; mt < 4; mt++)
#pragma unroll
        for (int nt = 0; nt < 4; nt++)
#pragma unroll
            for (int i = 0; i < 4; i++) acc[mt][nt][i] = 0.f;

    // prologue: tile 0
    float4 ra0 = *(const float4*)(aPtr);
    float4 ra1 = *(const float4*)(aPtr + 4);
    float4 rb0 = *(const float4*)(bPtr);
    float4 rb1 = *(const float4*)(bPtr + 4);
    *(float4*)&As[0][aRow][aK]     = f2tf4(ra0);
    *(float4*)&As[0][aRow][aK + 4] = f2tf4(ra1);
    *(float4*)&Bs[0][bRow][bCol]     = f2tf4(rb0);
    *(float4*)&Bs[0][bRow][bCol + 4] = f2tf4(rb1);
    __syncthreads();

#pragma unroll 1
    for (int k0 = 0; k0 < EE; k0 += 16) {
        int buf = (k0 >> 4) & 1;
        bool more = (k0 + 16) < EE;
        if (more) {
            ra0 = *(const float4*)(aPtr + k0 + 16);
            ra1 = *(const float4*)(aPtr + k0 + 20);
            rb0 = *(const float4*)(bPtr + (size_t)(k0 + 16) * QKVN);
            rb1 = *(const float4*)(bPtr + (size_t)(k0 + 16) * QKVN + 4);
        }
        GEMM_COMPUTE(As[buf], Bs[buf]);
        if (more) {
            *(float4*)&As[buf ^ 1][aRow][aK]     = f2tf4(ra0);
            *(float4*)&As[buf ^ 1][aRow][aK + 4] = f2tf4(ra1);
            *(float4*)&Bs[buf ^ 1][bRow][bCol]     = f2tf4(rb0);
            *(float4*)&Bs[buf ^ 1][bRow][bCol + 4] = f2tf4(rb1);
        }
        __syncthreads();
    }

    // epilogue: scatter into q/k/v [b,n,s,h] + bias
    int sel = colBlock / EE;
    const float* bias = (sel == 0) ? bq : (sel == 1) ? bk : bv;
    float* dst = (sel == 0) ? g_q : (sel == 1) ? g_k : g_v;
#pragma unroll
    for (int mt = 0; mt < 4; mt++) {
#pragma unroll
        for (int nt = 0; nt < 4; nt++) {
            int j  = colBlock + warpN * 32 + nt * 8 + 2 * t;
            int jr = j - sel * EE;
            int n  = jr >> 6;
            int h  = jr & 63;
            float b0 = bias[jr], b1 = bias[jr + 1];
            int r0 = rowBlock + warpM * 64 + mt * 16 + g;
            int r1 = r0 + 8;
            int bb0 = r0 >> 11, s0 = r0 & 2047;
            int bb1 = r1 >> 11, s1 = r1 & 2047;
            *(float2*)(dst + (((size_t)(bb0 * NHEAD + n) * SS) + s0) * HD + h) =
                make_float2(acc[mt][nt][0] + b0, acc[mt][nt][1] + b1);
            *(float2*)(dst + (((size_t)(bb1 * NHEAD + n) * SS) + s1) * HD + h) =
                make_float2(acc[mt][nt][2] + b0, acc[mt][nt][3] + b1);
        }
    }
}

// ---------------- flash attention (double-buffered K/V) ----------------
#define KS_PITCH 68
#define VS_PITCH 72
#define KS_SZ (64*KS_PITCH)
#define VS_SZ (64*VS_PITCH)
#define FLASH_SMEM ((2*KS_SZ + 2*VS_SZ)*4)

__global__ __launch_bounds__(256, 1) void flash_kernel() {
    extern __shared__ float fsm[];

    int tid = threadIdx.x;
    int wid = tid >> 5, lane = tid & 31;
    int g = lane >> 2, t = lane & 3;
    int bn = blockIdx.y;
    int qt = gridDim.x - 1 - blockIdx.x;   // heavy blocks first
    int q0 = qt * 128;

    const float* qb = g_q + (size_t)bn * SS * HD;
    const float* kb = g_k + (size_t)bn * SS * HD;
    const float* vb = g_v + (size_t)bn * SS * HD;

    int ldRow = tid >> 4;             // 0..15 base row
    int ldCol = (tid & 15) * 4;       // 0..60

    // Q fragments in registers, pre-scaled by 1/sqrt(64)
    int qrow = q0 + wid * 16;
    uint32_t qf[8][4];
#pragma unroll
    for (int ks = 0; ks < 8; ks++) {
        qf[ks][0] = f2tf(0.125f * qb[(size_t)(qrow + g) * HD + ks * 8 + t]);
        qf[ks][1] = f2tf(0.125f * qb[(size_t)(qrow + g + 8) * HD + ks * 8 + t]);
        qf[ks][2] = f2tf(0.125f * qb[(size_t)(qrow + g) * HD + ks * 8 + t + 4]);
        qf[ks][3] = f2tf(0.125f * qb[(size_t)(qrow + g + 8) * HD + ks * 8 + t + 4]);
    }

    float acc[8][4];
#pragma unroll
    for (int nt = 0; nt < 8; nt++)
#pragma unroll
        for (int i = 0; i < 4; i++) acc[nt][i] = 0.f;
    float m0 = -1e30f, m1 = -1e30f, l0 = 0.f, l1 = 0.f;

    int ntk = 2 * qt + 2;
    int r0 = qrow + g, r1 = qrow + g + 8;

    // prologue: load tile 0 into buffer 0
    float4 rk[4], rv[4];
#pragma unroll
    for (int i = 0; i < 4; i++) {
        int row = ldRow + i * 16;
        rk[i] = *(const float4*)(kb + (size_t)row * HD + ldCol);
        rv[i] = *(const float4*)(vb + (size_t)row * HD + ldCol);
    }
#pragma unroll
    for (int i = 0; i < 4; i++) {
        int row = ldRow + i * 16;
        *(float4*)&fsm[row * KS_PITCH + ldCol] = f2tf4(rk[i]);
        *(float4*)&fsm[2 * KS_SZ + row * VS_PITCH + ldCol] = f2tf4(rv[i]);
    }
    __syncthreads();

#pragma unroll 1
    for (int kt = 0; kt < ntk; kt++) {
        int buf = kt & 1;
        const float* Kb = fsm + buf * KS_SZ;
        const float* Vb = fsm + 2 * KS_SZ + buf * VS_SZ;
        int k0 = kt * 64;
        bool more = (kt + 1) < ntk;

        // S = Q K^T
        float sc[8][4];
#pragma unroll
        for (int nt = 0; nt < 8; nt++)
#pragma unroll
            for (int i = 0; i < 4; i++) sc[nt][i] = 0.f;
#pragma unroll
        for (int nt = 0; nt < 8; nt++) {
#pragma unroll
            for (int ks = 0; ks < 8; ks++) {
                uint32_t b0 = __float_as_uint(Kb[(nt * 8 + g) * KS_PITCH + ks * 8 + t]);
                uint32_t b1 = __float_as_uint(Kb[(nt * 8 + g) * KS_PITCH + ks * 8 + t + 4]);
                mma8(sc[nt], qf[ks], b0, b1);
            }
        }

        // causal mask (two diagonal tiles only)
        if (kt >= 2 * qt) {
#pragma unroll
            for (int nt = 0; nt < 8; nt++) {
                int cA = k0 + nt * 8 + 2 * t;
                int cB = cA + 1;
                if (cA > r0) sc[nt][0] = -1e30f;
                if (cB > r0) sc[nt][1] = -1e30f;
                if (cA > r1) sc[nt][2] = -1e30f;
                if (cB > r1) sc[nt][3] = -1e30f;
            }
        }

        // online softmax (quad reductions)
        float rm0 = -1e30f, rm1 = -1e30f;
#pragma unroll
        for (int nt = 0; nt < 8; nt++) {
            rm0 = fmaxf(rm0, fmaxf(sc[nt][0], sc[nt][1]));
            rm1 = fmaxf(rm1, fmaxf(sc[nt][2], sc[nt][3]));
        }
        rm0 = fmaxf(rm0, __shfl_xor_sync(0xffffffffu, rm0, 1));
        rm0 = fmaxf(rm0, __shfl_xor_sync(0xffffffffu, rm0, 2));
        rm1 = fmaxf(rm1, __shfl_xor_sync(0xffffffffu, rm1, 1));
        rm1 = fmaxf(rm1, __shfl_xor_sync(0xffffffffu, rm1, 2));
        float mn0 = fmaxf(m0, rm0), mn1 = fmaxf(m1, rm1);
        float al0 = __expf(m0 - mn0), al1 = __expf(m1 - mn1);
        m0 = mn0; m1 = mn1;

        float rs0 = 0.f, rs1 = 0.f;
#pragma unroll
        for (int nt = 0; nt < 8; nt++) {
            sc[nt][0] = __expf(sc[nt][0] - m0); rs0 += sc[nt][0];
            sc[nt][1] = __expf(sc[nt][1] - m0); rs0 += sc[nt][1];
            sc[nt][2] = __expf(sc[nt][2] - m1); rs1 += sc[nt][2];
            sc[nt][3] = __expf(sc[nt][3] - m1); rs1 += sc[nt][3];
        }
        rs0 += __shfl_xor_sync(0xffffffffu, rs0, 1);
        rs0 += __shfl_xor_sync(0xffffffffu, rs0, 2);
        rs1 += __shfl_xor_sync(0xffffffffu, rs1, 1);
        rs1 += __shfl_xor_sync(0xffffffffu, rs1, 2);
        l0 = l0 * al0 + rs0;
        l1 = l1 * al1 + rs1;
#pragma unroll
        for (int nt = 0; nt < 8; nt++) {
            acc[nt][0] *= al0; acc[nt][1] *= al0;
            acc[nt][2] *= al1; acc[nt][3] *= al1;
        }

        // prefetch next K/V tile (hide gmem latency under PV)
        if (more) {
            int nk0 = k0 + 64;
#pragma unroll
            for (int i = 0; i < 4; i++) {
                int row = nk0 + ldRow + i * 16;
                rk[i] = *(const float4*)(kb + (size_t)row * HD + ldCol);
                rv[i] = *(const float4*)(vb + (size_t)row * HD + ldCol);
            }
        }

        // O += P @ V  (C-frag -> A-frag transpose via quad shuffles)
        int src  = g * 4 + (t >> 1);
        int src2 = src + 2;
#pragma unroll
        for (int j = 0; j < 8; j++) {
            float x0 = __shfl_sync(0xffffffffu, sc[j][0], src);
            float x1 = __shfl_sync(0xffffffffu, sc[j][1], src);
            float y0 = __shfl_sync(0xffffffffu, sc[j][0], src2);
            float y1 = __shfl_sync(0xffffffffu, sc[j][1], src2);
            float z0 = __shfl_sync(0xffffffffu, sc[j][2], src);
            float z1 = __shfl_sync(0xffffffffu, sc[j][3], src);
            float w0 = __shfl_sync(0xffffffffu, sc[j][2], src2);
            float w1 = __shfl_sync(0xffffffffu, sc[j][3], src2);
            uint32_t pa[4];
            pa[0] = f2tf((t & 1) ? x1 : x0);
            pa[1] = f2tf((t & 1) ? z1 : z0);
            pa[2] = f2tf((t & 1) ? y1 : y0);
            pa[3] = f2tf((t & 1) ? w1 : w0);
#pragma unroll
            for (int hd = 0; hd < 8; hd++) {
                uint32_t b0 = __float_as_uint(Vb[(j * 8 + t) * VS_PITCH + hd * 8 + g]);
                uint32_t b1 = __float_as_uint(Vb[(j * 8 + t + 4) * VS_PITCH + hd * 8 + g]);
                mma8(acc[hd], pa, b0, b1);
            }
        }

        // store prefetched tile into the other buffer
        if (more) {
            float* Kn = fsm + (buf ^ 1) * KS_SZ;
            float* Vn = fsm + 2 * KS_SZ + (buf ^ 1) * VS_SZ;
#pragma unroll
            for (int i = 0; i < 4; i++) {
                int row = ldRow + i * 16;
                *(float4*)&Kn[row * KS_PITCH + ldCol] = f2tf4(rk[i]);
                *(float4*)&Vn[row * VS_PITCH + ldCol] = f2tf4(rv[i]);
            }
        }
        __syncthreads();
    }

    // epilogue -> g_z[b, s, n*64+h]
    int b_ = bn / NHEAD;
    int n_ = bn - b_ * NHEAD;
    float inv0 = 1.f / l0, inv1 = 1.f / l1;
#pragma unroll
    for (int hd = 0; hd < 8; hd++) {
        int h = hd * 8 + 2 * t;
        *(float2*)(g_z + ((size_t)(b_ * SS + r0) * NHEAD + n_) * HD + h) =
            make_float2(acc[hd][0] * inv0, acc[hd][1] * inv0);
        *(float2*)(g_z + ((size_t)(b_ * SS + r1) * NHEAD + n_) * HD + h) =
            make_float2(acc[hd][2] * inv1, acc[hd][3] * inv1);
    }
}

// ---------------- output GEMM ----------------
__global__ __launch_bounds__(256, 2) void out_gemm_kernel(
    const float* __restrict__ Bm, const float* __restrict__ bo,
    float* __restrict__ C) {
    __shared__ float As[2][128][20];
    __shared__ float Bs[2][16][136];

    int tid = threadIdx.x;
    int wid = tid >> 5, lane = tid & 31;
    int g = lane >> 2, t = lane & 3;
    int warpM = wid >> 2, warpN = wid & 3;
    int rowBlock = blockIdx.y * 128;
    int colBlock = blockIdx.x * 128;

    int aRow = tid >> 1, aK = (tid & 1) * 8;
    int bRow = tid >> 4, bCol = (tid & 15) * 8;

    const float* aPtr = g_z + (size_t)(rowBlock + aRow) * EE + aK;
    const float* bPtr = Bm + (size_t)bRow * EE + colBlock + bCol;

    float acc[4][4][4];
#pragma unroll
    for (int mt = 0; mt < 4; mt++)
#pragma unroll
        for (int nt = 0; nt < 4; nt++)
#pragma unroll
            for (int i = 0; i < 4; i++) acc[mt][nt][i] = 0.f;

    float4 ra0 = *(const float4*)(aPtr);
    float4 ra1 = *(const float4*)(aPtr + 4);
    float4 rb0 = *(const float4*)(bPtr);
    float4 rb1 = *(const float4*)(bPtr + 4);
    *(float4*)&As[0][aRow][aK]     = f2tf4(ra0);
    *(float4*)&As[0][aRow][aK + 4] = f2tf4(ra1);
    *(float4*)&Bs[0][bRow][bCol]     = f2tf4(rb0);
    *(float4*)&Bs[0][bRow][bCol + 4] = f2tf4(rb1);
    __syncthreads();

#pragma unroll 1
    for (int k0 = 0; k0 < EE; k0 += 16) {
        int buf = (k0 >> 4) & 1;
        bool more = (k0 + 16) < EE;
        if (more) {
            ra0 = *(const float4*)(aPtr + k0 + 16);
            ra1 = *(const float4*)(aPtr + k0 + 20);
            rb0 = *(const float4*)(bPtr + (size_t)(k0 + 16) * EE);
            rb1 = *(const float4*)(bPtr + (size_t)(k0 + 16) * EE + 4);
        }
        GEMM_COMPUTE(As[buf], Bs[buf]);
        if (more) {
            *(float4*)&As[buf ^ 1][aRow][aK]     = f2tf4(ra0);
            *(float4*)&As[buf ^ 1][aRow][aK + 4] = f2tf4(ra1);
            *(float4*)&Bs[buf ^ 1][bRow][bCol]     = f2tf4(rb0);
            *(float4*)&Bs[buf ^ 1][bRow][bCol + 4] = f2tf4(rb1);
        }
        __syncthreads();
    }

#pragma unroll
    for (int mt = 0; mt < 4; mt++) {
#pragma unroll
        for (int nt = 0; nt < 4; nt++) {
            int col = colBlock + warpN * 32 + nt * 8 + 2 * t;
            float b0 = bo[col], b1 = bo[col + 1];
            int r0 = rowBlock + warpM * 64 + mt * 16 + g;
            int r1 = r0 + 8;
            *(float2*)(C + (size_t)r0 * EE + col) =
                make_float2(acc[mt][nt][0] + b0, acc[mt][nt][1] + b1);
            *(float2*)(C + (size_t)r1 * EE + col) =
                make_float2(acc[mt][nt][2] + b0, acc[mt][nt][3] + b1);
        }
    }
}

// ---------------- launch ----------------
extern "C" void kernel_launch(void* const* d_in, const int* in_sizes, int n_in,
                              void* d_out, int out_size) {
    const float* x  = (const float*)d_in[0];
    const float* WQ = (const float*)d_in[1];
    const float* WK = (const float*)d_in[2];
    const float* WV = (const float*)d_in[3];
    const float* WO = (const float*)d_in[4];
    const float* bq = (const float*)d_in[5];
    const float* bk = (const float*)d_in[6];
    const float* bv = (const float*)d_in[7];
    const float* bo = (const float*)d_in[8];
    float* out = (float*)d_out;

    cudaFuncSetAttribute(flash_kernel,
                         cudaFuncAttributeMaxDynamicSharedMemorySize, FLASH_SMEM);

    pack_w_kernel<<<(EE * QKVN + 255) / 256, 256>>>(WQ, WK, WV);
    qkv_gemm_kernel<<<dim3(QKVN / 128, BSROWS / 128), 256>>>(x, bq, bk, bv);
    flash_kernel<<<dim3(SS / 128, BB * NHEAD), 256, FLASH_SMEM>>>();
    out_gemm_kernel<<<dim3(EE / 128, BSROWS / 128), 256>>>(WO, bo, out);
}

// round 5
// speedup vs baseline: 4.2356x; 1.1506x over previous
#include <cuda_runtime.h>
#include <cstdint>

#define BB 4
#define SS 2048
#define EE 768
#define NHEAD 12
#define HD 64
#define BSROWS (BB*SS)      // 8192
#define QKVN (3*EE)         // 2304

// ---------------- scratch ----------------
__device__ float g_Wp[EE*QKVN];            // packed [E, 3*N*H]
__device__ float g_q[BB*NHEAD*SS*HD];      // [b,n,s,h]
__device__ float g_k[BB*NHEAD*SS*HD];
__device__ float g_v[BB*NHEAD*SS*HD];
__device__ float g_z[BB*SS*EE];            // [b,s,n*h]

// ---------------- helpers ----------------
__device__ __forceinline__ uint32_t f2tf(float x) {
    uint32_t u;
    asm("cvt.rna.tf32.f32 %0, %1;" : "=r"(u) : "f"(x));
    return u;
}
__device__ __forceinline__ float f2tff(float x) {
    return __uint_as_float(f2tf(x));
}
__device__ __forceinline__ float4 f2tf4(float4 v) {
    return make_float4(f2tff(v.x), f2tff(v.y), f2tff(v.z), f2tff(v.w));
}
__device__ __forceinline__ void mma8(float* c, const uint32_t* a, uint32_t b0, uint32_t b1) {
    asm volatile(
        "mma.sync.aligned.m16n8k8.row.col.f32.tf32.tf32.f32 "
        "{%0,%1,%2,%3},{%4,%5,%6,%7},{%8,%9},{%0,%1,%2,%3};"
        : "+f"(c[0]), "+f"(c[1]), "+f"(c[2]), "+f"(c[3])
        : "r"(a[0]), "r"(a[1]), "r"(a[2]), "r"(a[3]), "r"(b0), "r"(b1));
}
__device__ __forceinline__ void ldsm4(uint32_t* r, uint32_t saddr) {
    asm volatile(
        "ldmatrix.sync.aligned.m8n8.x4.shared.b16 {%0,%1,%2,%3}, [%4];"
        : "=r"(r[0]), "=r"(r[1]), "=r"(r[2]), "=r"(r[3]) : "r"(saddr));
}
__device__ __forceinline__ uint32_t sptr(const void* p) {
    return (uint32_t)__cvta_generic_to_shared(p);
}

// ---------------- pack W_Q/W_K/W_V -> [E, 2304] ----------------
__global__ void pack_w_kernel(const float* __restrict__ WQ,
                              const float* __restrict__ WK,
                              const float* __restrict__ WV) {
    int idx = blockIdx.x * blockDim.x + threadIdx.x;
    if (idx >= EE * QKVN) return;
    int e   = idx / QKVN;
    int j   = idx - e * QKVN;
    int sel = j / EE;
    int jr  = j - sel * EE;
    int n   = jr >> 6;
    int h   = jr & 63;
    const float* W = (sel == 0) ? WQ : (sel == 1) ? WK : WV;
    g_Wp[idx] = W[(n * EE + e) * HD + h];
}

// ======== GEMM core: BM=128 BN=128 BK=16, 8 warps 2x4, warp 64x32, LDSM frags ========
// As: [m][k] pitch 20.  Bs: [n][16] n-major, phys col = k ^ (4*((n>>1)&3)).
// ks step on B = XOR of 32 bytes on the lane address (bit 3 of float col).
#define GEMM_COMPUTE(ASBASE, BSBASE)                                                \
    _Pragma("unroll")                                                               \
    for (int ks = 0; ks < 2; ks++) {                                                \
        uint32_t af[4][4];                                                          \
        _Pragma("unroll")                                                           \
        for (int mt = 0; mt < 4; mt++)                                              \
            ldsm4(af[mt], (ASBASE) + mt * (16 * 20 * 4) + ks * 32);                 \
        uint32_t bf0[4], bf2[4];                                                    \
        ldsm4(bf0, (BSBASE) ^ (ks * 32));                                           \
        ldsm4(bf2, ((BSBASE) + 16 * 16 * 4) ^ (ks * 32));                           \
        _Pragma("unroll")                                                           \
        for (int mt = 0; mt < 4; mt++) {                                            \
            mma8(acc[mt][0], af[mt], bf0[0], bf0[1]);                               \
            mma8(acc[mt][1], af[mt], bf0[2], bf0[3]);                               \
            mma8(acc[mt][2], af[mt], bf2[0], bf2[1]);                               \
            mma8(acc[mt][3], af[mt], bf2[2], bf2[3]);                               \
        }                                                                           \
    }

// ---------------- QKV GEMM ----------------
__global__ __launch_bounds__(256, 2) void qkv_gemm_kernel(
    const float* __restrict__ A,
    const float* __restrict__ bq, const float* __restrict__ bk,
    const float* __restrict__ bv) {
    __shared__ __align__(128) float As[2][128][20];
    __shared__ __align__(128) float Bs[2][128][16];

    int tid = threadIdx.x;
    int wid = tid >> 5, lane = tid & 31;
    int g = lane >> 2, t = lane & 3;
    int warpM = wid >> 2, warpN = wid & 3;
    int rowBlock = blockIdx.y * 128;
    int colBlock = blockIdx.x * 128;

    // A loader: row-major float4 pairs
    int aRow = tid >> 1, aK = (tid & 1) * 8;
    const float* aPtr = A + (size_t)(rowBlock + aRow) * EE + aK;

    // B loader: n = tid&127, k-half = (tid>>7)*8; strided LDG, swizzled STS.128
    int bN = tid & 127, bKh = (tid >> 7) * 8;
    const float* bPtr = g_Wp + (size_t)bKh * QKVN + colBlock + bN;
    int fB = 4 * ((bN >> 1) & 3);
    int sCol0 = (bKh + 0) ^ fB;   // contiguous float4 (fB in bits 2-3, bKh bit 3)
    int sCol1 = (bKh + 4) ^ fB;

    // LDSM addresses
    uint32_t aLd = sptr(&As[0][warpM * 64 + (lane & 15)][4 * (lane >> 4)]);
    int bRowL = warpN * 32 + (lane & 7) + 8 * (lane >> 4);
    int bColL = (4 * ((lane >> 3) & 1)) ^ (4 * ((bRowL >> 1) & 3));
    uint32_t bLd = sptr(&Bs[0][bRowL][bColL]);

    float acc[4][4][4];
#pragma unroll
    for (int mt = 0; mt < 4; mt++)
#pragma unroll
        for (int nt = 0; nt < 4; nt++)
#pragma unroll
            for (int i = 0; i < 4; i++) acc[mt][nt][i] = 0.f;

    // prologue
    float4 ra0 = *(const float4*)(aPtr);
    float4 ra1 = *(const float4*)(aPtr + 4);
    float rb[8];
#pragma unroll
    for (int i = 0; i < 8; i++) rb[i] = bPtr[(size_t)i * QKVN];
    *(float4*)&As[0][aRow][aK]     = f2tf4(ra0);
    *(float4*)&As[0][aRow][aK + 4] = f2tf4(ra1);
    *(float4*)&Bs[0][bN][sCol0] =
        make_float4(f2tff(rb[0]), f2tff(rb[1]), f2tff(rb[2]), f2tff(rb[3]));
    *(float4*)&Bs[0][bN][sCol1] =
        make_float4(f2tff(rb[4]), f2tff(rb[5]), f2tff(rb[6]), f2tff(rb[7]));
    __syncthreads();

#pragma unroll 1
    for (int k0 = 0; k0 < EE; k0 += 16) {
        int buf = (k0 >> 4) & 1;
        bool more = (k0 + 16) < EE;
        if (more) {
            ra0 = *(const float4*)(aPtr + k0 + 16);
            ra1 = *(const float4*)(aPtr + k0 + 20);
#pragma unroll
            for (int i = 0; i < 8; i++) rb[i] = bPtr[(size_t)(k0 + 16 + i) * QKVN];
        }
        {
            uint32_t aB = aLd + buf * (128 * 20 * 4);
            uint32_t bB = bLd + buf * (128 * 16 * 4);
            GEMM_COMPUTE(aB, bB);
        }
        if (more) {
            int nb = buf ^ 1;
            *(float4*)&As[nb][aRow][aK]     = f2tf4(ra0);
            *(float4*)&As[nb][aRow][aK + 4] = f2tf4(ra1);
            *(float4*)&Bs[nb][bN][sCol0] =
                make_float4(f2tff(rb[0]), f2tff(rb[1]), f2tff(rb[2]), f2tff(rb[3]));
            *(float4*)&Bs[nb][bN][sCol1] =
                make_float4(f2tff(rb[4]), f2tff(rb[5]), f2tff(rb[6]), f2tff(rb[7]));
        }
        __syncthreads();
    }

    // epilogue: scatter into q/k/v [b,n,s,h] + bias
    int sel = colBlock / EE;
    const float* bias = (sel == 0) ? bq : (sel == 1) ? bk : bv;
    float* dst = (sel == 0) ? g_q : (sel == 1) ? g_k : g_v;
#pragma unroll
    for (int mt = 0; mt < 4; mt++) {
#pragma unroll
        for (int nt = 0; nt < 4; nt++) {
            int j  = colBlock + warpN * 32 + nt * 8 + 2 * t;
            int jr = j - sel * EE;
            int n  = jr >> 6;
            int h  = jr & 63;
            float b0 = bias[jr], b1 = bias[jr + 1];
            int r0 = rowBlock + warpM * 64 + mt * 16 + g;
            int r1 = r0 + 8;
            int bb0 = r0 >> 11, s0 = r0 & 2047;
            int bb1 = r1 >> 11, s1 = r1 & 2047;
            *(float2*)(dst + (((size_t)(bb0 * NHEAD + n) * SS) + s0) * HD + h) =
                make_float2(acc[mt][nt][0] + b0, acc[mt][nt][1] + b1);
            *(float2*)(dst + (((size_t)(bb1 * NHEAD + n) * SS) + s1) * HD + h) =
                make_float2(acc[mt][nt][2] + b0, acc[mt][nt][3] + b1);
        }
    }
}

// ---------------- flash attention (double-buffered K/V, LDSM for K) ----------------
#define KS_PITCH 68
#define VS_PITCH 72
#define KS_SZ (64*KS_PITCH)
#define VS_SZ (64*VS_PITCH)
#define FLASH_SMEM ((2*KS_SZ + 2*VS_SZ)*4)

__global__ __launch_bounds__(256, 1) void flash_kernel() {
    extern __shared__ __align__(128) float fsm[];

    int tid = threadIdx.x;
    int wid = tid >> 5, lane = tid & 31;
    int g = lane >> 2, t = lane & 3;
    int bn = blockIdx.y;
    int qt = gridDim.x - 1 - blockIdx.x;   // heavy blocks first
    int q0 = qt * 128;

    const float* qb = g_q + (size_t)bn * SS * HD;
    const float* kb = g_k + (size_t)bn * SS * HD;
    const float* vb = g_v + (size_t)bn * SS * HD;

    int ldRow = tid >> 4;             // 0..15 base row
    int ldCol = (tid & 15) * 4;       // 0..60

    // K LDSM lane address: row = (lane&7) (+nt*8), col = 4*(lane>>3) (+ksp*16)
    uint32_t kLdBase = sptr(fsm) + ((lane & 7) * KS_PITCH + 4 * (lane >> 3)) * 4;

    // Q fragments in registers, pre-scaled by 1/sqrt(64)
    int qrow = q0 + wid * 16;
    uint32_t qf[8][4];
#pragma unroll
    for (int ks = 0; ks < 8; ks++) {
        qf[ks][0] = f2tf(0.125f * qb[(size_t)(qrow + g) * HD + ks * 8 + t]);
        qf[ks][1] = f2tf(0.125f * qb[(size_t)(qrow + g + 8) * HD + ks * 8 + t]);
        qf[ks][2] = f2tf(0.125f * qb[(size_t)(qrow + g) * HD + ks * 8 + t + 4]);
        qf[ks][3] = f2tf(0.125f * qb[(size_t)(qrow + g + 8) * HD + ks * 8 + t + 4]);
    }

    float acc[8][4];
#pragma unroll
    for (int nt = 0; nt < 8; nt++)
#pragma unroll
        for (int i = 0; i < 4; i++) acc[nt][i] = 0.f;
    float m0 = -1e30f, m1 = -1e30f, l0 = 0.f, l1 = 0.f;

    int ntk = 2 * qt + 2;
    int r0 = qrow + g, r1 = qrow + g + 8;

    // prologue: load tile 0 into buffer 0
    float4 rk[4], rv[4];
#pragma unroll
    for (int i = 0; i < 4; i++) {
        int row = ldRow + i * 16;
        rk[i] = *(const float4*)(kb + (size_t)row * HD + ldCol);
        rv[i] = *(const float4*)(vb + (size_t)row * HD + ldCol);
    }
#pragma unroll
    for (int i = 0; i < 4; i++) {
        int row = ldRow + i * 16;
        *(float4*)&fsm[row * KS_PITCH + ldCol] = f2tf4(rk[i]);
        *(float4*)&fsm[2 * KS_SZ + row * VS_PITCH + ldCol] = f2tf4(rv[i]);
    }
    __syncthreads();

#pragma unroll 1
    for (int kt = 0; kt < ntk; kt++) {
        int buf = kt & 1;
        uint32_t kLd = kLdBase + buf * (KS_SZ * 4);
        const float* Vb = fsm + 2 * KS_SZ + buf * VS_SZ;
        int k0 = kt * 64;
        bool more = (kt + 1) < ntk;

        // S = Q K^T  (K b-frags via LDSM.x4: 2 k-steps per load)
        float sc[8][4];
#pragma unroll
        for (int nt = 0; nt < 8; nt++)
#pragma unroll
            for (int i = 0; i < 4; i++) sc[nt][i] = 0.f;
#pragma unroll
        for (int nt = 0; nt < 8; nt++) {
            uint32_t rowAddr = kLd + nt * (8 * KS_PITCH * 4);
#pragma unroll
            for (int ksp = 0; ksp < 4; ksp++) {
                uint32_t kf[4];
                ldsm4(kf, rowAddr + ksp * 64);
                mma8(sc[nt], qf[2 * ksp],     kf[0], kf[1]);
                mma8(sc[nt], qf[2 * ksp + 1], kf[2], kf[3]);
            }
        }

        // causal mask (two diagonal tiles only)
        if (kt >= 2 * qt) {
#pragma unroll
            for (int nt = 0; nt < 8; nt++) {
                int cA = k0 + nt * 8 + 2 * t;
                int cB = cA + 1;
                if (cA > r0) sc[nt][0] = -1e30f;
                if (cB > r0) sc[nt][1] = -1e30f;
                if (cA > r1) sc[nt][2] = -1e30f;
                if (cB > r1) sc[nt][3] = -1e30f;
            }
        }

        // online softmax (quad reductions)
        float rm0 = -1e30f, rm1 = -1e30f;
#pragma unroll
        for (int nt = 0; nt < 8; nt++) {
            rm0 = fmaxf(rm0, fmaxf(sc[nt][0], sc[nt][1]));
            rm1 = fmaxf(rm1, fmaxf(sc[nt][2], sc[nt][3]));
        }
        rm0 = fmaxf(rm0, __shfl_xor_sync(0xffffffffu, rm0, 1));
        rm0 = fmaxf(rm0, __shfl_xor_sync(0xffffffffu, rm0, 2));
        rm1 = fmaxf(rm1, __shfl_xor_sync(0xffffffffu, rm1, 1));
        rm1 = fmaxf(rm1, __shfl_xor_sync(0xffffffffu, rm1, 2));
        float mn0 = fmaxf(m0, rm0), mn1 = fmaxf(m1, rm1);
        float al0 = __expf(m0 - mn0), al1 = __expf(m1 - mn1);
        m0 = mn0; m1 = mn1;

        float rs0 = 0.f, rs1 = 0.f;
#pragma unroll
        for (int nt = 0; nt < 8; nt++) {
            sc[nt][0] = __expf(sc[nt][0] - m0); rs0 += sc[nt][0];
            sc[nt][1] = __expf(sc[nt][1] - m0); rs0 += sc[nt][1];
            sc[nt][2] = __expf(sc[nt][2] - m1); rs1 += sc[nt][2];
            sc[nt][3] = __expf(sc[nt][3] - m1); rs1 += sc[nt][3];
        }
        rs0 += __shfl_xor_sync(0xffffffffu, rs0, 1);
        rs0 += __shfl_xor_sync(0xffffffffu, rs0, 2);
        rs1 += __shfl_xor_sync(0xffffffffu, rs1, 1);
        rs1 += __shfl_xor_sync(0xffffffffu, rs1, 2);
        l0 = l0 * al0 + rs0;
        l1 = l1 * al1 + rs1;
#pragma unroll
        for (int nt = 0; nt < 8; nt++) {
            acc[nt][0] *= al0; acc[nt][1] *= al0;
            acc[nt][2] *= al1; acc[nt][3] *= al1;
        }

        // prefetch next K/V tile
        if (more) {
            int nk0 = k0 + 64;
#pragma unroll
            for (int i = 0; i < 4; i++) {
                int row = nk0 + ldRow + i * 16;
                rk[i] = *(const float4*)(kb + (size_t)row * HD + ldCol);
                rv[i] = *(const float4*)(vb + (size_t)row * HD + ldCol);
            }
        }

        // O += P @ V  (C-frag -> A-frag transpose via quad shuffles)
        int src  = g * 4 + (t >> 1);
        int src2 = src + 2;
#pragma unroll
        for (int j = 0; j < 8; j++) {
            float x0 = __shfl_sync(0xffffffffu, sc[j][0], src);
            float x1 = __shfl_sync(0xffffffffu, sc[j][1], src);
            float y0 = __shfl_sync(0xffffffffu, sc[j][0], src2);
            float y1 = __shfl_sync(0xffffffffu, sc[j][1], src2);
            float z0 = __shfl_sync(0xffffffffu, sc[j][2], src);
            float z1 = __shfl_sync(0xffffffffu, sc[j][3], src);
            float w0 = __shfl_sync(0xffffffffu, sc[j][2], src2);
            float w1 = __shfl_sync(0xffffffffu, sc[j][3], src2);
            uint32_t pa[4];
            pa[0] = f2tf((t & 1) ? x1 : x0);
            pa[1] = f2tf((t & 1) ? z1 : z0);
            pa[2] = f2tf((t & 1) ? y1 : y0);
            pa[3] = f2tf((t & 1) ? w1 : w0);
#pragma unroll
            for (int hd = 0; hd < 8; hd++) {
                uint32_t b0 = __float_as_uint(Vb[(j * 8 + t) * VS_PITCH + hd * 8 + g]);
                uint32_t b1 = __float_as_uint(Vb[(j * 8 + t + 4) * VS_PITCH + hd * 8 + g]);
                mma8(acc[hd], pa, b0, b1);
            }
        }

        // store prefetched tile into the other buffer
        if (more) {
            float* Kn = fsm + (buf ^ 1) * KS_SZ;
            float* Vn = fsm + 2 * KS_SZ + (buf ^ 1) * VS_SZ;
#pragma unroll
            for (int i = 0; i < 4; i++) {
                int row = ldRow + i * 16;
                *(float4*)&Kn[row * KS_PITCH + ldCol] = f2tf4(rk[i]);
                *(float4*)&Vn[row * VS_PITCH + ldCol] = f2tf4(rv[i]);
            }
        }
        __syncthreads();
    }

    // epilogue -> g_z[b, s, n*64+h]
    int b_ = bn / NHEAD;
    int n_ = bn - b_ * NHEAD;
    float inv0 = 1.f / l0, inv1 = 1.f / l1;
#pragma unroll
    for (int hd = 0; hd < 8; hd++) {
        int h = hd * 8 + 2 * t;
        *(float2*)(g_z + ((size_t)(b_ * SS + r0) * NHEAD + n_) * HD + h) =
            make_float2(acc[hd][0] * inv0, acc[hd][1] * inv0);
        *(float2*)(g_z + ((size_t)(b_ * SS + r1) * NHEAD + n_) * HD + h) =
            make_float2(acc[hd][2] * inv1, acc[hd][3] * inv1);
    }
}

// ---------------- output GEMM ----------------
__global__ __launch_bounds__(256, 2) void out_gemm_kernel(
    const float* __restrict__ Bm, const float* __restrict__ bo,
    float* __restrict__ C) {
    __shared__ __align__(128) float As[2][128][20];
    __shared__ __align__(128) float Bs[2][128][16];

    int tid = threadIdx.x;
    int wid = tid >> 5, lane = tid & 31;
    int g = lane >> 2, t = lane & 3;
    int warpM = wid >> 2, warpN = wid & 3;
    int rowBlock = blockIdx.y * 128;
    int colBlock = blockIdx.x * 128;

    int aRow = tid >> 1, aK = (tid & 1) * 8;
    const float* aPtr = g_z + (size_t)(rowBlock + aRow) * EE + aK;

    int bN = tid & 127, bKh = (tid >> 7) * 8;
    const float* bPtr = Bm + (size_t)bKh * EE + colBlock + bN;
    int fB = 4 * ((bN >> 1) & 3);
    int sCol0 = (bKh + 0) ^ fB;
    int sCol1 = (bKh + 4) ^ fB;

    uint32_t aLd = sptr(&As[0][warpM * 64 + (lane & 15)][4 * (lane >> 4)]);
    int bRowL = warpN * 32 + (lane & 7) + 8 * (lane >> 4);
    int bColL = (4 * ((lane >> 3) & 1)) ^ (4 * ((bRowL >> 1) & 3));
    uint32_t bLd = sptr(&Bs[0][bRowL][bColL]);

    float acc[4][4][4];
#pragma unroll
    for (int mt = 0; mt < 4; mt++)
#pragma unroll
        for (int nt = 0; nt < 4; nt++)
#pragma unroll
            for (int i = 0; i < 4; i++) acc[mt][nt][i] = 0.f;

    float4 ra0 = *(const float4*)(aPtr);
    float4 ra1 = *(const float4*)(aPtr + 4);
    float rb[8];
#pragma unroll
    for (int i = 0; i < 8; i++) rb[i] = bPtr[(size_t)i * EE];
    *(float4*)&As[0][aRow][aK]     = f2tf4(ra0);
    *(float4*)&As[0][aRow][aK + 4] = f2tf4(ra1);
    *(float4*)&Bs[0][bN][sCol0] =
        make_float4(f2tff(rb[0]), f2tff(rb[1]), f2tff(rb[2]), f2tff(rb[3]));
    *(float4*)&Bs[0][bN][sCol1] =
        make_float4(f2tff(rb[4]), f2tff(rb[5]), f2tff(rb[6]), f2tff(rb[7]));
    __syncthreads();

#pragma unroll 1
    for (int k0 = 0; k0 < EE; k0 += 16) {
        int buf = (k0 >> 4) & 1;
        bool more = (k0 + 16) < EE;
        if (more) {
            ra0 = *(const float4*)(aPtr + k0 + 16);
            ra1 = *(const float4*)(aPtr + k0 + 20);
#pragma unroll
            for (int i = 0; i < 8; i++) rb[i] = bPtr[(size_t)(k0 + 16 + i) * EE];
        }
        {
            uint32_t aB = aLd + buf * (128 * 20 * 4);
            uint32_t bB = bLd + buf * (128 * 16 * 4);
            GEMM_COMPUTE(aB, bB);
        }
        if (more) {
            int nb = buf ^ 1;
            *(float4*)&As[nb][aRow][aK]     = f2tf4(ra0);
            *(float4*)&As[nb][aRow][aK + 4] = f2tf4(ra1);
            *(float4*)&Bs[nb][bN][sCol0] =
                make_float4(f2tff(rb[0]), f2tff(rb[1]), f2tff(rb[2]), f2tff(rb[3]));
            *(float4*)&Bs[nb][bN][sCol1] =
                make_float4(f2tff(rb[4]), f2tff(rb[5]), f2tff(rb[6]), f2tff(rb[7]));
        }
        __syncthreads();
    }

#pragma unroll
    for (int mt = 0; mt < 4; mt++) {
#pragma unroll
        for (int nt = 0; nt < 4; nt++) {
            int col = colBlock + warpN * 32 + nt * 8 + 2 * t;
            float b0 = bo[col], b1 = bo[col + 1];
            int r0 = rowBlock + warpM * 64 + mt * 16 + g;
            int r1 = r0 + 8;
            *(float2*)(C + (size_t)r0 * EE + col) =
                make_float2(acc[mt][nt][0] + b0, acc[mt][nt][1] + b1);
            *(float2*)(C + (size_t)r1 * EE + col) =
                make_float2(acc[mt][nt][2] + b0, acc[mt][nt][3] + b1);
        }
    }
}

// ---------------- launch ----------------
extern "C" void kernel_launch(void* const* d_in, const int* in_sizes, int n_in,
                              void* d_out, int out_size) {
    const float* x  = (const float*)d_in[0];
    const float* WQ = (const float*)d_in[1];
    const float* WK = (const float*)d_in[2];
    const float* WV = (const float*)d_in[3];
    const float* WO = (const float*)d_in[4];
    const float* bq = (const float*)d_in[5];
    const float* bk = (const float*)d_in[6];
    const float* bv = (const float*)d_in[7];
    const float* bo = (const float*)d_in[8];
    float* out = (float*)d_out;

    cudaFuncSetAttribute(flash_kernel,
                         cudaFuncAttributeMaxDynamicSharedMemorySize, FLASH_SMEM);

    pack_w_kernel<<<(EE * QKVN + 255) / 256, 256>>>(WQ, WK, WV);
    qkv_gemm_kernel<<<dim3(QKVN / 128, BSROWS / 128), 256>>>(x, bq, bk, bv);
    flash_kernel<<<dim3(SS / 128, BB * NHEAD), 256, FLASH_SMEM>>>();
    out_gemm_kernel<<<dim3(EE / 128, BSROWS / 128), 256>>>(WO, bo, out);
}